// round 10
// baseline (speedup 1.0000x reference)
#include <cuda_runtime.h>
#include <cstdint>
#include <cstddef>

// Problem constants
#define BQ    8
#define CIN   64
#define TLEN  1024
#define FF    256
#define COUT  64
#define GG    32
#define UU    8

// Tiling
#define O_PER_CTA 32
#define TILE_T    128
#define ICHUNK    16
#define NCHUNK    (CIN / ICHUNK)     // 4

// SMEM layout (floats)
#define WS_FLOATS   (4 * CIN * 64)          // ws[up][i][o*2+j] : 16384
#define XS_TSTRIDE  10                       // 8 data + 2 pad
#define XS_ISTRIDE  (TILE_T * XS_TSTRIDE)    // 1280
#define XS_BUF      (ICHUNK * XS_ISTRIDE)    // 20480
#define XS_FLOATS   (2 * XS_BUF)             // 40960
#define SMEM_BYTES  ((WS_FLOATS + XS_FLOATS) * 4)   // 229376 <= 232448
#define YS_TSTRIDE  258                      // y-stage [t][o*8+u], 2-pad per t

typedef unsigned long long ull;

__device__ __forceinline__ void fma2(ull& d, ull a, ull b) {
    asm("fma.rn.f32x2 %0, %1, %2, %0;" : "+l"(d) : "l"(a), "l"(b));
}
__device__ __forceinline__ float2 unpack2(ull v) {
    unsigned lo, hi;
    asm("mov.b64 {%0, %1}, %2;" : "=r"(lo), "=r"(hi) : "l"(v));
    return make_float2(__uint_as_float(lo), __uint_as_float(hi));
}
__device__ __forceinline__ void cp_async8(uint32_t dst, const void* src) {
    asm volatile("cp.async.ca.shared.global [%0], [%1], 8;\n" :: "r"(dst), "l"(src));
}
__device__ __forceinline__ void cp_commit() {
    asm volatile("cp.async.commit_group;\n" ::: "memory");
}
template <int N>
__device__ __forceinline__ void cp_wait() {
    asm volatile("cp.async.wait_group %0;\n" :: "n"(N) : "memory");
}

__global__ void __launch_bounds__(512, 1)
grouped_linear_cf_kernel(const float* __restrict__ x,
                         const float* __restrict__ w,
                         const float* __restrict__ bias,
                         float* __restrict__ y)
{
    extern __shared__ float smem[];
    float* ws = smem;                 // [up][i][o*2+j]  (j = u low/high of pair)
    float* xs = smem + WS_FLOATS;     // [buf][i_local][t][u] stride-10
    float* ys = xs;                   // epilogue stage reuses x buffers

    const int g   = blockIdx.x;
    const int b   = blockIdx.y;
    const int oh  = blockIdx.z & 1;        // o-half
    const int tz  = blockIdx.z >> 1;       // t-range (8 x 128)
    const int tid = threadIdx.x;

    const int lane = tid & 31;
    const int warp = tid >> 5;
    const int up   = warp & 3;             // u-pair
    const int og   = (warp >> 2) & 1;      // o-sixteen
    const int tsub = warp >> 3;            // t-subtile (64 each)
    const int u0   = up * 2;
    const int t0   = tz * TILE_T;

    const float* xg = x + (size_t)b * CIN * TLEN * FF + (size_t)g * UU;

    // ---- prologue: cp.async chunk 0 into buf 0 ----
    {
#pragma unroll
        for (int kk = 0; kk < 16; ++kk) {
            int idx = tid + kk * 512;          // 8192: 16i x 128t x 4seg
            int il  = idx >> 9;
            int rem = idx & 511;
            int t   = rem >> 2;
            int seg = rem & 3;
            const float* src = xg + (size_t)il * (TLEN * FF)
                                  + (size_t)(t0 + t) * FF + seg * 2;
            uint32_t dst = (uint32_t)__cvta_generic_to_shared(
                xs + il * XS_ISTRIDE + t * XS_TSTRIDE + seg * 2);
            cp_async8(dst, src);
        }
        cp_commit();
    }

    // ---- weights -> SMEM (once): ws[up][i][o*2+j] = w[g][2up+j][i][oh*32+o] ----
    {
        const float* wgl = w + (size_t)g * (UU * CIN * COUT) + oh * O_PER_CTA;
#pragma unroll
        for (int kk = 0; kk < 32; ++kk) {
            int idx = tid + kk * 512;          // 16384: 8u x 64i x 32o
            int uu  = idx >> 11;
            int i   = (idx >> 5) & 63;
            int o   = idx & 31;
            ws[(uu >> 1) * (CIN * 64) + i * 64 + o * 2 + (uu & 1)] =
                wgl[((size_t)uu * CIN + i) * COUT + o];
        }
    }

    ull acc[2][16];
#pragma unroll
    for (int tt = 0; tt < 2; ++tt)
#pragma unroll
        for (int oo = 0; oo < 16; ++oo) acc[tt][oo] = 0ull;

    for (int ic = 0; ic < NCHUNK; ++ic) {
        if (ic + 1 < NCHUNK) {
            float* dstb = xs + ((ic + 1) & 1) * XS_BUF;
            const int ibase = (ic + 1) * ICHUNK;
#pragma unroll
            for (int kk = 0; kk < 16; ++kk) {
                int idx = tid + kk * 512;
                int il  = idx >> 9;
                int rem = idx & 511;
                int t   = rem >> 2;
                int seg = rem & 3;
                const float* src = xg + (size_t)(ibase + il) * (TLEN * FF)
                                      + (size_t)(t0 + t) * FF + seg * 2;
                uint32_t dst = (uint32_t)__cvta_generic_to_shared(
                    dstb + il * XS_ISTRIDE + t * XS_TSTRIDE + seg * 2);
                cp_async8(dst, src);
            }
            cp_commit();
            cp_wait<1>();
        } else {
            cp_wait<0>();
        }
        __syncthreads();

        const float* xb = xs + (ic & 1) * XS_BUF + (tsub * 64 + lane) * XS_TSTRIDE + u0;
        const float* wb = ws + up * (CIN * 64) + og * 32 + ic * ICHUNK * 64;

#pragma unroll 2
        for (int il = 0; il < ICHUNK; ++il) {
            // x u-pairs for this lane's two t positions (t, t+32)
            ull xv0 = *reinterpret_cast<const ull*>(xb + il * XS_ISTRIDE);
            ull xv1 = *reinterpret_cast<const ull*>(xb + il * XS_ISTRIDE + 32 * XS_TSTRIDE);

            // 16 o-pairs of w, warp-uniform broadcast (all lanes same address)
            const float* wr = wb + il * 64;
#pragma unroll
            for (int k = 0; k < 8; ++k) {
                ulonglong2 wq = *reinterpret_cast<const ulonglong2*>(wr + k * 4);
                fma2(acc[0][2 * k],     xv0, wq.x);
                fma2(acc[0][2 * k + 1], xv0, wq.y);
                fma2(acc[1][2 * k],     xv1, wq.x);
                fma2(acc[1][2 * k + 1], xv1, wq.y);
            }
        }
        __syncthreads();
    }

    // ---- epilogue: stage through smem for full-sector stores ----
    // write: ys[t][o*8 + u]  (t-stride 258 -> 2-phase conflict-free STS.64)
#pragma unroll
    for (int tt = 0; tt < 2; ++tt) {
        const int t = tsub * 64 + tt * 32 + lane;
#pragma unroll
        for (int oo = 0; oo < 16; ++oo) {
            const int o = og * 16 + oo;
            *reinterpret_cast<float2*>(ys + t * YS_TSTRIDE + o * 8 + u0) =
                unpack2(acc[tt][oo]);
        }
    }
    __syncthreads();

    // read + coalesced store: each (t,o) row is 8 floats = one full 32B sector
    float* yb = y + (size_t)b * COUT * TLEN * FF;
#pragma unroll
    for (int kk = 0; kk < 16; ++kk) {
        int idx = tid + kk * 512;          // 8192: 32o x 128t x 2s
        int o   = idx >> 8;
        int rem = idx & 255;
        int t   = rem >> 1;
        int s   = rem & 1;
        const float* r = ys + t * YS_TSTRIDE + o * 8 + s * 4;
        float2 a = *reinterpret_cast<const float2*>(r);
        float2 c = *reinterpret_cast<const float2*>(r + 2);
        float4 bb = *reinterpret_cast<const float4*>(
            bias + (size_t)(oh * O_PER_CTA + o) * FF + g * UU + s * 4);
        float4 out = make_float4(a.x + bb.x, a.y + bb.y, c.x + bb.z, c.y + bb.w);
        *reinterpret_cast<float4*>(
            yb + ((size_t)(oh * O_PER_CTA + o) * TLEN + t0 + t) * FF + g * UU + s * 4) = out;
    }
}

extern "C" void kernel_launch(void* const* d_in, const int* in_sizes, int n_in,
                              void* d_out, int out_size) {
    (void)in_sizes; (void)n_in; (void)out_size;
    const float* x    = (const float*)d_in[0];
    const float* w    = (const float*)d_in[1];
    const float* bias = (const float*)d_in[2];
    float*       y    = (float*)d_out;

    cudaFuncSetAttribute(grouped_linear_cf_kernel,
                         cudaFuncAttributeMaxDynamicSharedMemorySize, SMEM_BYTES);

    dim3 grid(GG, BQ, 16);   // 32 g x 8 b x (2 o-halves * 8 t-ranges) = 4096 CTAs
    grouped_linear_cf_kernel<<<grid, 512, SMEM_BYTES>>>(x, w, bias, y);
}